// round 2
// baseline (speedup 1.0000x reference)
#include <cuda_runtime.h>
#include <math.h>

#define N_ROWS   16384
#define ACTIONS  64
#define EMB      32
#define DELTA    16
#define EPSF     1e-5f
#define NB1      128
#define ROWS_PER_B1 (N_ROWS / NB1)   // 128

// Scratch (no allocation allowed in kernel_launch): partial sums + BN params.
__device__ float g_psum[NB1][ACTIONS];
__device__ float g_psq [NB1][ACTIONS];
__device__ float g_scale[ACTIONS];
__device__ float g_shift[ACTIONS];

// ---------------------------------------------------------------------------
// Kernel 1: per-block partial sum / sumsq per action column.
// Thread layout: c = tid & 63 (column), r4 = tid >> 6 (row quarter, 0..3).
// A warp reads 32 consecutive columns of one row -> fully coalesced 128B.
// Deterministic: fixed-order intra-block reduction, no atomics.
// ---------------------------------------------------------------------------
__global__ __launch_bounds__(256) void bn_partial(const float* __restrict__ x)
{
    const int tid = threadIdx.x;
    const int c   = tid & 63;
    const int r4  = tid >> 6;
    const int b   = blockIdx.x;

    const float* px = x + (size_t)(b * ROWS_PER_B1 + r4) * ACTIONS + c;
    float s = 0.f, q = 0.f;
#pragma unroll 8
    for (int k = 0; k < ROWS_PER_B1 / 4; k++) {
        float v = px[(size_t)k * 4 * ACTIONS];
        s += v;
        q += v * v;
    }

    __shared__ float ss[4][ACTIONS];
    __shared__ float sq[4][ACTIONS];
    ss[r4][c] = s;
    sq[r4][c] = q;
    __syncthreads();

    if (r4 == 0) {
        float ts = ((ss[0][c] + ss[1][c]) + ss[2][c]) + ss[3][c];
        float tq = ((sq[0][c] + sq[1][c]) + sq[2][c]) + sq[3][c];
        g_psum[b][c] = ts;
        g_psq [b][c] = tq;
    }
}

// ---------------------------------------------------------------------------
// Kernel 2: finalize BN stats -> per-column scale/shift. 64 threads, tiny.
// Sequential fixed-order reduction over the 128 partials (deterministic).
// ---------------------------------------------------------------------------
__global__ void bn_finalize(const float* __restrict__ wgt,
                            const float* __restrict__ bias)
{
    const int c = threadIdx.x;
    float s = 0.f, q = 0.f;
    for (int j = 0; j < NB1; j++) {
        s += g_psum[j][c];
        q += g_psq [j][c];
    }
    const float inv_n = 1.0f / (float)N_ROWS;
    float mean = s * inv_n;
    float var  = fmaf(-mean, mean, q * inv_n);   // E[x^2] - mean^2
    float sc   = wgt[c] * rsqrtf(var + EPSF);
    g_scale[c] = sc;
    g_shift[c] = fmaf(-mean, sc, bias[c]);
}

// ---------------------------------------------------------------------------
// Kernel 3: main spline-embedding pass.
//  - 8 lanes per (row, action) pair; lane handles one float4 of EMB=32.
//  - blockIdx.y = action  =>  per-block table working set = 33 rows * 128B
//    = 4.2 KB -> gathers are L1-resident after warmup.
//  - xh = xl + 1 always, so bh is bl's row + 64; wl = 1 - wh exactly.
//  - Streaming store (__stcs) keeps the write stream from polluting L2.
// ---------------------------------------------------------------------------
__global__ __launch_bounds__(256) void spline_main(const float* __restrict__ x,
                                                   const float* __restrict__ emb,
                                                   float* __restrict__ out)
{
    const int tid   = threadIdx.x;
    const int lane8 = tid & 7;        // float4 group within EMB
    const int pi    = tid >> 3;       // pair index within block (0..31)
    const int a     = blockIdx.y;
    const int row   = blockIdx.x * 32 + pi;

    const float sc = g_scale[a];
    const float sh = g_shift[a];

    const float xv = __ldg(x + (size_t)row * ACTIONS + a);
    float t = tanhf(fmaf(xv, sc, sh));
    t = fminf(fmaxf(t, -1.0f + 1e-5f), 1.0f - 1e-5f);

    const float f   = t * (float)DELTA;       // exact (power-of-2 scale)
    const float xlf = floorf(f);
    const float wh  = f - xlf;                // = DELTA*(t - xl)
    const float wl  = 1.0f - wh;              // = DELTA*(xh - t)

    const int li = (((int)xlf) + DELTA) * ACTIONS + a;   // bl table row

    const float4* bl4 = reinterpret_cast<const float4*>(emb)
                      + (size_t)li * (EMB / 4) + lane8;
    const float4 bl = __ldg(bl4);
    const float4 bh = __ldg(bl4 + (size_t)ACTIONS * (EMB / 4)); // row + 64

    float4 h;
    h.x = bh.x * wh + bl.x * wl;
    h.y = bh.y * wh + bl.y * wl;
    h.z = bh.z * wh + bl.z * wl;
    h.w = bh.w * wh + bl.w * wl;

    float4* o4 = reinterpret_cast<float4*>(out)
               + (size_t)(row * ACTIONS + a) * (EMB / 4) + lane8;
    __stcs(o4, h);
}

// ---------------------------------------------------------------------------
// Launch: x, bn_weight, bn_bias, emb_table  ->  out [n, ACTIONS, EMB] fp32
// ---------------------------------------------------------------------------
extern "C" void kernel_launch(void* const* d_in, const int* in_sizes, int n_in,
                              void* d_out, int out_size)
{
    const float* x    = (const float*)d_in[0];
    const float* wgt  = (const float*)d_in[1];
    const float* bias = (const float*)d_in[2];
    const float* emb  = (const float*)d_in[3];
    float* out        = (float*)d_out;

    bn_partial<<<NB1, 256>>>(x);
    bn_finalize<<<1, ACTIONS>>>(wgt, bias);

    dim3 grid(N_ROWS / 32, ACTIONS);
    spline_main<<<grid, 256>>>(x, emb, out);
}